// round 1
// baseline (speedup 1.0000x reference)
#include <cuda_runtime.h>

#define BATCH  2
#define SEQ    4096
#define DMODEL 512
#define NHEAD  8
#define DKH    64
#define MTOT   (BATCH * SEQ)

// Scratch (allocation-free rule: __device__ globals)
__device__ float g_Q[(size_t)MTOT * DMODEL];
__device__ float g_K[(size_t)MTOT * DMODEL];
__device__ float g_V[(size_t)MTOT * DMODEL];
__device__ float g_AO[(size_t)MTOT * DMODEL];

// ---------------------------------------------------------------------------
// Projection GEMM: C[M,512] = A[M,512] @ W[512,512]^T + bias
// 128x128 tile, BK=16, 256 threads, 8x8 per thread.
// ---------------------------------------------------------------------------
__global__ __launch_bounds__(256) void proj_kernel(
        const float* __restrict__ A, const float* __restrict__ W,
        const float* __restrict__ bias, float* __restrict__ C) {
    const int BK = 16;
    __shared__ float As[BK][132];   // [k][m], padded ld=132 (16B-aligned rows)
    __shared__ float Bs[BK][132];   // [k][n]

    const int tid = threadIdx.x;
    const int ty = tid >> 4;        // 0..15 -> C rows ty*8..+7
    const int tx = tid & 15;        // 0..15 -> C cols tx*8..+7
    const int bm = blockIdx.x * 128;
    const int bn = blockIdx.y * 128;

    const int lrow = tid >> 2;          // 0..63
    const int lg   = (tid & 3) * 4;     // k offset in tile

    float acc[8][8];
    #pragma unroll
    for (int i = 0; i < 8; i++)
        #pragma unroll
        for (int j = 0; j < 8; j++) acc[i][j] = 0.f;

    for (int k0 = 0; k0 < DMODEL; k0 += BK) {
        #pragma unroll
        for (int p = 0; p < 2; p++) {
            int r = lrow + p * 64;
            float4 va = *(const float4*)(A + (size_t)(bm + r) * DMODEL + k0 + lg);
            As[lg + 0][r] = va.x; As[lg + 1][r] = va.y;
            As[lg + 2][r] = va.z; As[lg + 3][r] = va.w;
            float4 vb = *(const float4*)(W + (size_t)(bn + r) * DMODEL + k0 + lg);
            Bs[lg + 0][r] = vb.x; Bs[lg + 1][r] = vb.y;
            Bs[lg + 2][r] = vb.z; Bs[lg + 3][r] = vb.w;
        }
        __syncthreads();
        #pragma unroll
        for (int kk = 0; kk < BK; kk++) {
            float a[8], b[8];
            *(float4*)&a[0] = *(const float4*)&As[kk][ty * 8];
            *(float4*)&a[4] = *(const float4*)&As[kk][ty * 8 + 4];
            *(float4*)&b[0] = *(const float4*)&Bs[kk][tx * 8];
            *(float4*)&b[4] = *(const float4*)&Bs[kk][tx * 8 + 4];
            #pragma unroll
            for (int i = 0; i < 8; i++)
                #pragma unroll
                for (int j = 0; j < 8; j++)
                    acc[i][j] = fmaf(a[i], b[j], acc[i][j]);
        }
        __syncthreads();
    }

    float bb[8];
    #pragma unroll
    for (int j = 0; j < 8; j++) bb[j] = bias[bn + tx * 8 + j];

    #pragma unroll
    for (int i = 0; i < 8; i++) {
        size_t row = (size_t)(bm + ty * 8 + i);
        float* cp = C + row * DMODEL + bn + tx * 8;
        float4 o0 = make_float4(acc[i][0] + bb[0], acc[i][1] + bb[1],
                                acc[i][2] + bb[2], acc[i][3] + bb[3]);
        float4 o1 = make_float4(acc[i][4] + bb[4], acc[i][5] + bb[5],
                                acc[i][6] + bb[6], acc[i][7] + bb[7]);
        *(float4*)cp = o0;
        *(float4*)(cp + 4) = o1;
    }
}

// ---------------------------------------------------------------------------
// Flash attention (fp32). One CTA = 128 query rows of one (b,h).
// Streams 128-wide KV tiles with online softmax.
// Thread layout: 256 threads, ty=tid/16 owns 8 q-rows, tx=tid%16.
//   S tile (128x128): thread -> s[8][8]  (rows 8ty.., cols 8tx..)
//   O tile (128x64):  thread -> acc[8][4] (rows 8ty.., cols 4tx..)
// ---------------------------------------------------------------------------
#define QT_OFF 0                       // Qt[64][132]  (k-major, transposed)
#define KT_OFF (64 * 132)              // Kt[64][132]
#define VS_OFF (KT_OFF + 64 * 132)     // Vs[128][68]  (row-major: [kv][d])
#define PR_OFF (VS_OFF + 128 * 68)     // Pr[128][132] (row-major: [qrow][kv])
#define SMEM_FLOATS (PR_OFF + 128 * 132)
#define SMEM_BYTES  (SMEM_FLOATS * 4)

__global__ __launch_bounds__(256, 1) void attn_kernel() {
    extern __shared__ float sm[];
    float* Qt = sm + QT_OFF;
    float* Kt = sm + KT_OFF;
    float* Vs = sm + VS_OFF;
    float* Pr = sm + PR_OFF;

    const int tid = threadIdx.x;
    const int ty = tid >> 4;
    const int tx = tid & 15;
    const int qt = blockIdx.x;   // 0..31
    const int h  = blockIdx.y;   // 0..7
    const int b  = blockIdx.z;   // 0..1

    const float* Qg = g_Q + ((size_t)b * SEQ + qt * 128) * DMODEL + h * DKH;
    const float* Kg = g_K + (size_t)b * SEQ * DMODEL + h * DKH;
    const float* Vg = g_V + (size_t)b * SEQ * DMODEL + h * DKH;

    // Load Q tile (128x64) transposed into Qt[k][m]
    {
        const int f = (tid & 15) * 4;   // col offset 0..60
        const int r0 = tid >> 4;        // 16 rows per pass
        #pragma unroll
        for (int p = 0; p < 8; p++) {
            int r = r0 + p * 16;
            float4 v = *(const float4*)(Qg + (size_t)r * DMODEL + f);
            Qt[(f + 0) * 132 + r] = v.x; Qt[(f + 1) * 132 + r] = v.y;
            Qt[(f + 2) * 132 + r] = v.z; Qt[(f + 3) * 132 + r] = v.w;
        }
    }

    float m_i[8], l_i[8], acc[8][4];
    #pragma unroll
    for (int i = 0; i < 8; i++) {
        m_i[i] = -1e30f; l_i[i] = 0.f;
        #pragma unroll
        for (int c = 0; c < 4; c++) acc[i][c] = 0.f;
    }

    for (int it = 0; it < SEQ / 128; it++) {
        __syncthreads();  // previous tile's smem reads complete
        // Load K tile transposed, V tile direct
        {
            const int f = (tid & 15) * 4;
            const int r0 = tid >> 4;
            const float* Kb = Kg + (size_t)(it * 128) * DMODEL;
            const float* Vb = Vg + (size_t)(it * 128) * DMODEL;
            #pragma unroll
            for (int p = 0; p < 8; p++) {
                int r = r0 + p * 16;
                float4 v = *(const float4*)(Kb + (size_t)r * DMODEL + f);
                Kt[(f + 0) * 132 + r] = v.x; Kt[(f + 1) * 132 + r] = v.y;
                Kt[(f + 2) * 132 + r] = v.z; Kt[(f + 3) * 132 + r] = v.w;
                float4 w = *(const float4*)(Vb + (size_t)r * DMODEL + f);
                *(float4*)&Vs[r * 68 + f] = w;
            }
        }
        __syncthreads();

        // S = Q @ K^T  (128x128), k over 64
        float s[8][8];
        #pragma unroll
        for (int i = 0; i < 8; i++)
            #pragma unroll
            for (int j = 0; j < 8; j++) s[i][j] = 0.f;

        #pragma unroll 8
        for (int kk = 0; kk < DKH; kk++) {
            float a[8], kb[8];
            *(float4*)&a[0]  = *(const float4*)&Qt[kk * 132 + ty * 8];
            *(float4*)&a[4]  = *(const float4*)&Qt[kk * 132 + ty * 8 + 4];
            *(float4*)&kb[0] = *(const float4*)&Kt[kk * 132 + tx * 8];
            *(float4*)&kb[4] = *(const float4*)&Kt[kk * 132 + tx * 8 + 4];
            #pragma unroll
            for (int i = 0; i < 8; i++)
                #pragma unroll
                for (int j = 0; j < 8; j++)
                    s[i][j] = fmaf(a[i], kb[j], s[i][j]);
        }

        // Online softmax per row (row = 16 tx-lanes; shfl_xor within half-warp)
        const float scale = 0.125f;   // 1/sqrt(64)
        #pragma unroll
        for (int i = 0; i < 8; i++) {
            float mx = -1e30f;
            #pragma unroll
            for (int j = 0; j < 8; j++) { s[i][j] *= scale; mx = fmaxf(mx, s[i][j]); }
            #pragma unroll
            for (int o = 8; o >= 1; o >>= 1)
                mx = fmaxf(mx, __shfl_xor_sync(0xffffffffu, mx, o));
            float mnew = fmaxf(m_i[i], mx);
            float rs = 0.f;
            #pragma unroll
            for (int j = 0; j < 8; j++) {
                float p = __expf(s[i][j] - mnew);
                s[i][j] = p; rs += p;
            }
            #pragma unroll
            for (int o = 8; o >= 1; o >>= 1)
                rs += __shfl_xor_sync(0xffffffffu, rs, o);
            float alpha = __expf(m_i[i] - mnew);
            l_i[i] = l_i[i] * alpha + rs;
            m_i[i] = mnew;
            #pragma unroll
            for (int c = 0; c < 4; c++) acc[i][c] *= alpha;
        }

        // Write P row-major (float4, aligned: 132 % 4 == 0)
        #pragma unroll
        for (int i = 0; i < 8; i++) {
            *(float4*)&Pr[(ty * 8 + i) * 132 + tx * 8]     =
                make_float4(s[i][0], s[i][1], s[i][2], s[i][3]);
            *(float4*)&Pr[(ty * 8 + i) * 132 + tx * 8 + 4] =
                make_float4(s[i][4], s[i][5], s[i][6], s[i][7]);
        }
        __syncthreads();

        // O += P @ V  (128x64), kv over 128, unrolled by 4
        for (int kk = 0; kk < 128; kk += 4) {
            float4 a4[8];
            #pragma unroll
            for (int i = 0; i < 8; i++)
                a4[i] = *(const float4*)&Pr[(ty * 8 + i) * 132 + kk];
            #pragma unroll
            for (int t = 0; t < 4; t++) {
                float4 bv = *(const float4*)&Vs[(kk + t) * 68 + tx * 4];
                #pragma unroll
                for (int i = 0; i < 8; i++) {
                    float av = (t == 0) ? a4[i].x : (t == 1) ? a4[i].y
                             : (t == 2) ? a4[i].z : a4[i].w;
                    acc[i][0] = fmaf(av, bv.x, acc[i][0]);
                    acc[i][1] = fmaf(av, bv.y, acc[i][1]);
                    acc[i][2] = fmaf(av, bv.z, acc[i][2]);
                    acc[i][3] = fmaf(av, bv.w, acc[i][3]);
                }
            }
        }
    }

    // Epilogue: O / l  -> g_AO (concat-head layout)
    float* Og = g_AO + ((size_t)b * SEQ + qt * 128) * DMODEL + h * DKH;
    #pragma unroll
    for (int i = 0; i < 8; i++) {
        float inv = 1.f / l_i[i];
        float4 v = make_float4(acc[i][0] * inv, acc[i][1] * inv,
                               acc[i][2] * inv, acc[i][3] * inv);
        *(float4*)(Og + (size_t)(ty * 8 + i) * DMODEL + tx * 4) = v;
    }
}

// ---------------------------------------------------------------------------
extern "C" void kernel_launch(void* const* d_in, const int* in_sizes, int n_in,
                              void* d_out, int out_size) {
    const float* q   = (const float*)d_in[0];
    const float* k   = (const float*)d_in[1];
    const float* v   = (const float*)d_in[2];
    const float* w_q = (const float*)d_in[3];
    const float* b_q = (const float*)d_in[4];
    const float* w_k = (const float*)d_in[5];
    const float* b_k = (const float*)d_in[6];
    const float* w_v = (const float*)d_in[7];
    const float* b_v = (const float*)d_in[8];
    const float* w_o = (const float*)d_in[9];
    const float* b_o = (const float*)d_in[10];

    float *Q, *K, *V, *AO;
    cudaGetSymbolAddress((void**)&Q,  g_Q);
    cudaGetSymbolAddress((void**)&K,  g_K);
    cudaGetSymbolAddress((void**)&V,  g_V);
    cudaGetSymbolAddress((void**)&AO, g_AO);

    cudaFuncSetAttribute(attn_kernel,
                         cudaFuncAttributeMaxDynamicSharedMemorySize, SMEM_BYTES);

    dim3 pgrid(MTOT / 128, DMODEL / 128);
    proj_kernel<<<pgrid, 256>>>(q, w_q, b_q, Q);
    proj_kernel<<<pgrid, 256>>>(k, w_k, b_k, K);
    proj_kernel<<<pgrid, 256>>>(v, w_v, b_v, V);

    attn_kernel<<<dim3(SEQ / 128, NHEAD, BATCH), 256, SMEM_BYTES>>>();

    proj_kernel<<<pgrid, 256>>>(AO, w_o, b_o, (float*)d_out);
}

// round 2
// speedup vs baseline: 2.9792x; 2.9792x over previous
#include <cuda_runtime.h>
#include <cuda_fp16.h>
#include <cstdint>

#define BATCH  2
#define SEQ    4096
#define DMODEL 512
#define NHEAD  8
#define DKH    64
#define MTOT   (BATCH * SEQ)

// Scratch (__device__ globals: allocation-free rule)
__device__ __half g_Qh[(size_t)MTOT * DMODEL];
__device__ __half g_Kh[(size_t)MTOT * DMODEL];
__device__ __half g_Vh[(size_t)MTOT * DMODEL];
__device__ __half g_Vt[(size_t)MTOT * DMODEL];   // [b][h][d][s]
__device__ float  g_AO[(size_t)MTOT * DMODEL];

// ---------------------------------------------------------------------------
// Projection GEMM: C[M,512] = A[M,512] @ W[512,512]^T + bias  (fp32 compute)
// Output type templated: fp32 (final proj) or fp16 (q/k/v for tensor attn).
// ---------------------------------------------------------------------------
template <typename OutT>
__global__ __launch_bounds__(256) void proj_kernel(
        const float* __restrict__ A, const float* __restrict__ W,
        const float* __restrict__ bias, OutT* __restrict__ C) {
    const int BK = 16;
    __shared__ float As[BK][132];
    __shared__ float Bs[BK][132];

    const int tid = threadIdx.x;
    const int ty = tid >> 4;
    const int tx = tid & 15;
    const int bm = blockIdx.x * 128;
    const int bn = blockIdx.y * 128;

    const int lrow = tid >> 2;
    const int lg   = (tid & 3) * 4;

    float acc[8][8];
    #pragma unroll
    for (int i = 0; i < 8; i++)
        #pragma unroll
        for (int j = 0; j < 8; j++) acc[i][j] = 0.f;

    for (int k0 = 0; k0 < DMODEL; k0 += BK) {
        #pragma unroll
        for (int p = 0; p < 2; p++) {
            int r = lrow + p * 64;
            float4 va = *(const float4*)(A + (size_t)(bm + r) * DMODEL + k0 + lg);
            As[lg + 0][r] = va.x; As[lg + 1][r] = va.y;
            As[lg + 2][r] = va.z; As[lg + 3][r] = va.w;
            float4 vb = *(const float4*)(W + (size_t)(bn + r) * DMODEL + k0 + lg);
            Bs[lg + 0][r] = vb.x; Bs[lg + 1][r] = vb.y;
            Bs[lg + 2][r] = vb.z; Bs[lg + 3][r] = vb.w;
        }
        __syncthreads();
        #pragma unroll
        for (int kk = 0; kk < BK; kk++) {
            float a[8], b[8];
            *(float4*)&a[0] = *(const float4*)&As[kk][ty * 8];
            *(float4*)&a[4] = *(const float4*)&As[kk][ty * 8 + 4];
            *(float4*)&b[0] = *(const float4*)&Bs[kk][tx * 8];
            *(float4*)&b[4] = *(const float4*)&Bs[kk][tx * 8 + 4];
            #pragma unroll
            for (int i = 0; i < 8; i++)
                #pragma unroll
                for (int j = 0; j < 8; j++)
                    acc[i][j] = fmaf(a[i], b[j], acc[i][j]);
        }
        __syncthreads();
    }

    float bb[8];
    #pragma unroll
    for (int j = 0; j < 8; j++) bb[j] = bias[bn + tx * 8 + j];

    #pragma unroll
    for (int i = 0; i < 8; i++) {
        size_t row = (size_t)(bm + ty * 8 + i);
        float o[8];
        #pragma unroll
        for (int j = 0; j < 8; j++) o[j] = acc[i][j] + bb[j];

        if constexpr (sizeof(OutT) == 4) {
            float* cp = (float*)C + row * DMODEL + bn + tx * 8;
            *(float4*)cp       = make_float4(o[0], o[1], o[2], o[3]);
            *(float4*)(cp + 4) = make_float4(o[4], o[5], o[6], o[7]);
        } else {
            __half* cp = (__half*)C + row * DMODEL + bn + tx * 8;
            uint32_t pk[4];
            #pragma unroll
            for (int j = 0; j < 4; j++) {
                __half2 h = __floats2half2_rn(o[2 * j], o[2 * j + 1]);
                pk[j] = *(uint32_t*)&h;
            }
            *(uint4*)cp = make_uint4(pk[0], pk[1], pk[2], pk[3]);
        }
    }
}

// ---------------------------------------------------------------------------
// V transpose: g_Vh [b][s][h*64+d] -> g_Vt [(b*8+h)*64+d][s]
// ---------------------------------------------------------------------------
__global__ void vtrans_kernel(const __half* __restrict__ Vh,
                              __half* __restrict__ Vt) {
    __shared__ __half tile[32][33];
    const int bh = blockIdx.z;
    const int b = bh >> 3, h = bh & 7;
    const int s0 = blockIdx.x * 32;
    const int d0 = blockIdx.y * 32;
    const int tx = threadIdx.x, ty = threadIdx.y;  // 32x8

    #pragma unroll
    for (int i = 0; i < 4; i++) {
        int s = s0 + ty + i * 8;
        tile[ty + i * 8][tx] =
            Vh[((size_t)b * SEQ + s) * DMODEL + h * DKH + d0 + tx];
    }
    __syncthreads();
    #pragma unroll
    for (int i = 0; i < 4; i++) {
        int d = d0 + ty + i * 8;
        Vt[((size_t)bh * DKH + d) * SEQ + s0 + tx] = tile[tx][ty + i * 8];
    }
}

// ---------------------------------------------------------------------------
// Flash attention, fp16 mma.sync.m16n8k16 with fp32 accumulation.
// CTA = 128 q-rows of one (b,h); 8 warps; warp w owns q-rows 16w..16w+15
// and the full 128-col KV tile (row reductions stay in-warp).
// ---------------------------------------------------------------------------
#define QS_LD 72      // halves per row (pad: conflict-free A-frag loads)
#define KS_LD 72
#define VT_LD 136
#define QS_OFF 0
#define KS_OFF (128 * QS_LD)
#define VT_OFF (KS_OFF + 128 * KS_LD)
#define ATTN_SMEM_HALVES (VT_OFF + 64 * VT_LD)
#define ATTN_SMEM_BYTES  (ATTN_SMEM_HALVES * 2)

__device__ __forceinline__ void mma16816(float* d, const uint32_t* a,
                                         uint32_t b0, uint32_t b1) {
    asm volatile(
        "mma.sync.aligned.m16n8k16.row.col.f32.f16.f16.f32 "
        "{%0,%1,%2,%3}, {%4,%5,%6,%7}, {%8,%9}, {%0,%1,%2,%3};\n"
        : "+f"(d[0]), "+f"(d[1]), "+f"(d[2]), "+f"(d[3])
        : "r"(a[0]), "r"(a[1]), "r"(a[2]), "r"(a[3]), "r"(b0), "r"(b1));
}

__device__ __forceinline__ uint32_t pack_h2(float x, float y) {
    __half2 h = __floats2half2_rn(x, y);
    return *(uint32_t*)&h;
}

__global__ __launch_bounds__(256, 1) void attn_kernel(
        const __half* __restrict__ Qh, const __half* __restrict__ Kh,
        const __half* __restrict__ Vt, float* __restrict__ AO) {
    extern __shared__ __half sm[];
    __half* Qs  = sm + QS_OFF;
    __half* Ks  = sm + KS_OFF;
    __half* Vts = sm + VT_OFF;

    const int tid = threadIdx.x;
    const int w = tid >> 5;          // warp 0..7
    const int l = tid & 31;
    const int g = l >> 2;            // group row 0..7
    const int t = l & 3;

    const int qt = blockIdx.x;
    const int h  = blockIdx.y;
    const int b  = blockIdx.z;

    const __half* Qg = Qh + ((size_t)b * SEQ + qt * 128) * DMODEL + h * DKH;
    const __half* Kg = Kh + (size_t)b * SEQ * DMODEL + h * DKH;
    const __half* Vg = Vt + (size_t)(b * NHEAD + h) * DKH * SEQ;

    // Load Q tile (128 x 64 halves): 1024 uint4, 4 per thread
    #pragma unroll
    for (int j = 0; j < 4; j++) {
        int u = tid + 256 * j;
        int r = u >> 3, c8 = u & 7;
        uint4 v = *(const uint4*)(Qg + (size_t)r * DMODEL + c8 * 8);
        *(uint4*)&Qs[r * QS_LD + c8 * 8] = v;
    }

    float m0 = -1e30f, m1 = -1e30f, l0 = 0.f, l1 = 0.f;
    float o[8][4];
    #pragma unroll
    for (int dt = 0; dt < 8; dt++)
        #pragma unroll
        for (int c = 0; c < 4; c++) o[dt][c] = 0.f;

    const int r0 = 16 * w + g;

    for (int it = 0; it < SEQ / 128; it++) {
        __syncthreads();
        // K tile (128 x 64), V^T tile (64 x 128)
        #pragma unroll
        for (int j = 0; j < 4; j++) {
            int u = tid + 256 * j;
            int r = u >> 3, c8 = u & 7;
            uint4 v = *(const uint4*)(Kg + ((size_t)(it * 128 + r)) * DMODEL + c8 * 8);
            *(uint4*)&Ks[r * KS_LD + c8 * 8] = v;
        }
        #pragma unroll
        for (int j = 0; j < 4; j++) {
            int u = tid + 256 * j;
            int d = u >> 4, c16 = u & 15;
            uint4 v = *(const uint4*)(Vg + (size_t)d * SEQ + it * 128 + c16 * 8);
            *(uint4*)&Vts[d * VT_LD + c16 * 8] = v;
        }
        __syncthreads();

        // ---- S = Q @ K^T : s[16 n-tiles][4] ----
        float s[16][4];
        #pragma unroll
        for (int nt = 0; nt < 16; nt++)
            #pragma unroll
            for (int c = 0; c < 4; c++) s[nt][c] = 0.f;

        #pragma unroll
        for (int ks = 0; ks < 4; ks++) {
            const int k0 = 16 * ks;
            uint32_t a[4];
            a[0] = *(const uint32_t*)&Qs[(r0)     * QS_LD + k0 + 2 * t];
            a[1] = *(const uint32_t*)&Qs[(r0 + 8) * QS_LD + k0 + 2 * t];
            a[2] = *(const uint32_t*)&Qs[(r0)     * QS_LD + k0 + 2 * t + 8];
            a[3] = *(const uint32_t*)&Qs[(r0 + 8) * QS_LD + k0 + 2 * t + 8];
            #pragma unroll
            for (int nt = 0; nt < 16; nt++) {
                uint32_t b0 = *(const uint32_t*)&Ks[(8 * nt + g) * KS_LD + k0 + 2 * t];
                uint32_t b1 = *(const uint32_t*)&Ks[(8 * nt + g) * KS_LD + k0 + 2 * t + 8];
                mma16816(s[nt], a, b0, b1);
            }
        }

        // ---- online softmax (rows r0 and r0+8) ----
        const float scale = 0.125f;
        float mx0 = -1e30f, mx1 = -1e30f;
        #pragma unroll
        for (int nt = 0; nt < 16; nt++) {
            s[nt][0] *= scale; s[nt][1] *= scale;
            s[nt][2] *= scale; s[nt][3] *= scale;
            mx0 = fmaxf(mx0, fmaxf(s[nt][0], s[nt][1]));
            mx1 = fmaxf(mx1, fmaxf(s[nt][2], s[nt][3]));
        }
        #pragma unroll
        for (int ofs = 1; ofs <= 2; ofs <<= 1) {
            mx0 = fmaxf(mx0, __shfl_xor_sync(0xffffffffu, mx0, ofs));
            mx1 = fmaxf(mx1, __shfl_xor_sync(0xffffffffu, mx1, ofs));
        }
        const float mn0 = fmaxf(m0, mx0);
        const float mn1 = fmaxf(m1, mx1);
        float rs0 = 0.f, rs1 = 0.f;
        #pragma unroll
        for (int nt = 0; nt < 16; nt++) {
            s[nt][0] = __expf(s[nt][0] - mn0);
            s[nt][1] = __expf(s[nt][1] - mn0);
            s[nt][2] = __expf(s[nt][2] - mn1);
            s[nt][3] = __expf(s[nt][3] - mn1);
            rs0 += s[nt][0] + s[nt][1];
            rs1 += s[nt][2] + s[nt][3];
        }
        #pragma unroll
        for (int ofs = 1; ofs <= 2; ofs <<= 1) {
            rs0 += __shfl_xor_sync(0xffffffffu, rs0, ofs);
            rs1 += __shfl_xor_sync(0xffffffffu, rs1, ofs);
        }
        const float al0 = __expf(m0 - mn0);
        const float al1 = __expf(m1 - mn1);
        l0 = l0 * al0 + rs0;  m0 = mn0;
        l1 = l1 * al1 + rs1;  m1 = mn1;
        #pragma unroll
        for (int dt = 0; dt < 8; dt++) {
            o[dt][0] *= al0; o[dt][1] *= al0;
            o[dt][2] *= al1; o[dt][3] *= al1;
        }

        // ---- O += P @ V : P from registers (C-frag -> A-frag identity) ----
        #pragma unroll
        for (int ks = 0; ks < 8; ks++) {
            uint32_t a[4];
            a[0] = pack_h2(s[2 * ks][0],     s[2 * ks][1]);
            a[1] = pack_h2(s[2 * ks][2],     s[2 * ks][3]);
            a[2] = pack_h2(s[2 * ks + 1][0], s[2 * ks + 1][1]);
            a[3] = pack_h2(s[2 * ks + 1][2], s[2 * ks + 1][3]);
            const int k0 = 16 * ks;
            #pragma unroll
            for (int dt = 0; dt < 8; dt++) {
                uint32_t b0 = *(const uint32_t*)&Vts[(8 * dt + g) * VT_LD + k0 + 2 * t];
                uint32_t b1 = *(const uint32_t*)&Vts[(8 * dt + g) * VT_LD + k0 + 2 * t + 8];
                mma16816(o[dt], a, b0, b1);
            }
        }
    }

    // Epilogue: divide by l, write fp32 to g_AO (concat-head layout)
    float* Og = AO + ((size_t)b * SEQ + qt * 128) * DMODEL + h * DKH;
    const float inv0 = 1.f / l0, inv1 = 1.f / l1;
    #pragma unroll
    for (int dt = 0; dt < 8; dt++) {
        const int c = 8 * dt + 2 * t;
        *(float2*)(Og + (size_t)(r0)     * DMODEL + c) =
            make_float2(o[dt][0] * inv0, o[dt][1] * inv0);
        *(float2*)(Og + (size_t)(r0 + 8) * DMODEL + c) =
            make_float2(o[dt][2] * inv1, o[dt][3] * inv1);
    }
}

// ---------------------------------------------------------------------------
extern "C" void kernel_launch(void* const* d_in, const int* in_sizes, int n_in,
                              void* d_out, int out_size) {
    const float* q   = (const float*)d_in[0];
    const float* k   = (const float*)d_in[1];
    const float* v   = (const float*)d_in[2];
    const float* w_q = (const float*)d_in[3];
    const float* b_q = (const float*)d_in[4];
    const float* w_k = (const float*)d_in[5];
    const float* b_k = (const float*)d_in[6];
    const float* w_v = (const float*)d_in[7];
    const float* b_v = (const float*)d_in[8];
    const float* w_o = (const float*)d_in[9];
    const float* b_o = (const float*)d_in[10];

    __half *Qh, *Kh, *Vh, *Vt;
    float *AO;
    cudaGetSymbolAddress((void**)&Qh, g_Qh);
    cudaGetSymbolAddress((void**)&Kh, g_Kh);
    cudaGetSymbolAddress((void**)&Vh, g_Vh);
    cudaGetSymbolAddress((void**)&Vt, g_Vt);
    cudaGetSymbolAddress((void**)&AO, g_AO);

    cudaFuncSetAttribute(attn_kernel,
                         cudaFuncAttributeMaxDynamicSharedMemorySize,
                         ATTN_SMEM_BYTES);

    dim3 pgrid(MTOT / 128, DMODEL / 128);
    proj_kernel<__half><<<pgrid, 256>>>(q, w_q, b_q, Qh);
    proj_kernel<__half><<<pgrid, 256>>>(k, w_k, b_k, Kh);
    proj_kernel<__half><<<pgrid, 256>>>(v, w_v, b_v, Vh);

    vtrans_kernel<<<dim3(SEQ / 32, DKH / 32, BATCH * NHEAD), dim3(32, 8)>>>(Vh, Vt);

    attn_kernel<<<dim3(SEQ / 128, NHEAD, BATCH), 256, ATTN_SMEM_BYTES>>>(Qh, Kh, Vt, AO);

    proj_kernel<float><<<pgrid, 256>>>(AO, w_o, b_o, (float*)d_out);
}

// round 3
// speedup vs baseline: 4.8085x; 1.6140x over previous
#include <cuda_runtime.h>
#include <cuda_fp16.h>
#include <cstdint>

#define BATCH  2
#define SEQ    4096
#define DMODEL 512
#define NHEAD  8
#define DKH    64
#define MTOT   (BATCH * SEQ)

// Scratch (__device__ globals: allocation-free rule)
__device__ __half g_Qh[(size_t)MTOT * DMODEL];
__device__ __half g_Kh[(size_t)MTOT * DMODEL];
__device__ __half g_Vh[(size_t)MTOT * DMODEL];
__device__ __half g_Vt[(size_t)MTOT * DMODEL];   // [b][h][d][s]
__device__ float  g_AO[(size_t)MTOT * DMODEL];

// ---------------------------------------------------------------------------
// mma.sync helpers
// ---------------------------------------------------------------------------
__device__ __forceinline__ void mma16816(float* d, const uint32_t* a,
                                         uint32_t b0, uint32_t b1) {
    asm volatile(
        "mma.sync.aligned.m16n8k16.row.col.f32.f16.f16.f32 "
        "{%0,%1,%2,%3}, {%4,%5,%6,%7}, {%8,%9}, {%0,%1,%2,%3};\n"
        : "+f"(d[0]), "+f"(d[1]), "+f"(d[2]), "+f"(d[3])
        : "r"(a[0]), "r"(a[1]), "r"(a[2]), "r"(a[3]), "r"(b0), "r"(b1));
}

__device__ __forceinline__ uint32_t pack_h2(float x, float y) {
    __half2 h = __floats2half2_rn(x, y);
    return *(uint32_t*)&h;
}

// ---------------------------------------------------------------------------
// Tensor-core projection GEMM: C[M,512] = A[M,512] @ W[512,512]^T + bias
// fp32 inputs converted to fp16 during smem staging; fp32 accumulate.
// CTA tile 128x128, BK=64, 8 warps (4m x 2n), warp tile 32x64.
// ---------------------------------------------------------------------------
#define PLD 72   // halves per smem row (pad)

template <typename OutT>
__global__ __launch_bounds__(256) void proj16_kernel(
        const float* __restrict__ A, const float* __restrict__ W,
        const float* __restrict__ bias, OutT* __restrict__ C) {
    __shared__ __half As[128 * PLD];
    __shared__ __half Ws[128 * PLD];

    const int tid = threadIdx.x;
    const int w = tid >> 5;
    const int l = tid & 31;
    const int g = l >> 2;          // 0..7
    const int t = l & 3;           // 0..3
    const int wm = (w >> 1) * 32;  // warp m offset in tile
    const int wn = (w & 1) * 64;   // warp n offset in tile
    const int bm = blockIdx.x * 128;
    const int bn = blockIdx.y * 128;

    float acc[2][8][4];
    #pragma unroll
    for (int mt = 0; mt < 2; mt++)
        #pragma unroll
        for (int nt = 0; nt < 8; nt++)
            #pragma unroll
            for (int c = 0; c < 4; c++) acc[mt][nt][c] = 0.f;

    for (int k0 = 0; k0 < DMODEL; k0 += 64) {
        // Stage A and W tiles (128 x 64 fp32 -> fp16)
        #pragma unroll
        for (int j = 0; j < 8; j++) {
            int u = tid + 256 * j;
            int r = u >> 4, c4 = u & 15;
            float4 va = *(const float4*)(A + (size_t)(bm + r) * DMODEL + k0 + c4 * 4);
            *(uint2*)&As[r * PLD + c4 * 4] =
                make_uint2(pack_h2(va.x, va.y), pack_h2(va.z, va.w));
            float4 vb = *(const float4*)(W + (size_t)(bn + r) * DMODEL + k0 + c4 * 4);
            *(uint2*)&Ws[r * PLD + c4 * 4] =
                make_uint2(pack_h2(vb.x, vb.y), pack_h2(vb.z, vb.w));
        }
        __syncthreads();

        #pragma unroll
        for (int kk = 0; kk < 4; kk++) {
            const int ko = kk * 16 + 2 * t;
            uint32_t a[2][4];
            #pragma unroll
            for (int mt = 0; mt < 2; mt++) {
                const int r0 = wm + 16 * mt + g;
                a[mt][0] = *(const uint32_t*)&As[(r0)     * PLD + ko];
                a[mt][1] = *(const uint32_t*)&As[(r0 + 8) * PLD + ko];
                a[mt][2] = *(const uint32_t*)&As[(r0)     * PLD + ko + 8];
                a[mt][3] = *(const uint32_t*)&As[(r0 + 8) * PLD + ko + 8];
            }
            #pragma unroll
            for (int nt = 0; nt < 8; nt++) {
                const int nr = wn + 8 * nt + g;
                uint32_t b0 = *(const uint32_t*)&Ws[nr * PLD + ko];
                uint32_t b1 = *(const uint32_t*)&Ws[nr * PLD + ko + 8];
                mma16816(acc[0][nt], a[0], b0, b1);
                mma16816(acc[1][nt], a[1], b0, b1);
            }
        }
        __syncthreads();
    }

    // Epilogue: add bias, store
    #pragma unroll
    for (int mt = 0; mt < 2; mt++) {
        const int r0 = bm + wm + 16 * mt + g;
        #pragma unroll
        for (int nt = 0; nt < 8; nt++) {
            const int c = bn + wn + 8 * nt + 2 * t;
            const float b0 = bias[c], b1 = bias[c + 1];
            if constexpr (sizeof(OutT) == 4) {
                *(float2*)((float*)C + (size_t)(r0)     * DMODEL + c) =
                    make_float2(acc[mt][nt][0] + b0, acc[mt][nt][1] + b1);
                *(float2*)((float*)C + (size_t)(r0 + 8) * DMODEL + c) =
                    make_float2(acc[mt][nt][2] + b0, acc[mt][nt][3] + b1);
            } else {
                *(uint32_t*)((__half*)C + (size_t)(r0)     * DMODEL + c) =
                    pack_h2(acc[mt][nt][0] + b0, acc[mt][nt][1] + b1);
                *(uint32_t*)((__half*)C + (size_t)(r0 + 8) * DMODEL + c) =
                    pack_h2(acc[mt][nt][2] + b0, acc[mt][nt][3] + b1);
            }
        }
    }
}

// ---------------------------------------------------------------------------
// V transpose: g_Vh [b][s][h*64+d] -> g_Vt [(b*8+h)*64+d][s]
// ---------------------------------------------------------------------------
__global__ void vtrans_kernel(const __half* __restrict__ Vh,
                              __half* __restrict__ Vt) {
    __shared__ __half tile[32][33];
    const int bh = blockIdx.z;
    const int b = bh >> 3, h = bh & 7;
    const int s0 = blockIdx.x * 32;
    const int d0 = blockIdx.y * 32;
    const int tx = threadIdx.x, ty = threadIdx.y;  // 32x8

    #pragma unroll
    for (int i = 0; i < 4; i++) {
        int s = s0 + ty + i * 8;
        tile[ty + i * 8][tx] =
            Vh[((size_t)b * SEQ + s) * DMODEL + h * DKH + d0 + tx];
    }
    __syncthreads();
    #pragma unroll
    for (int i = 0; i < 4; i++) {
        int d = d0 + ty + i * 8;
        Vt[((size_t)bh * DKH + d) * SEQ + s0 + tx] = tile[tx][ty + i * 8];
    }
}

// ---------------------------------------------------------------------------
// Flash attention, fp16 mma with fp32 accumulation (unchanged from R2).
// ---------------------------------------------------------------------------
#define QS_LD 72
#define KS_LD 72
#define VT_LD 136
#define QS_OFF 0
#define KS_OFF (128 * QS_LD)
#define VT_OFF (KS_OFF + 128 * KS_LD)
#define ATTN_SMEM_HALVES (VT_OFF + 64 * VT_LD)
#define ATTN_SMEM_BYTES  (ATTN_SMEM_HALVES * 2)

__global__ __launch_bounds__(256, 1) void attn_kernel(
        const __half* __restrict__ Qh, const __half* __restrict__ Kh,
        const __half* __restrict__ Vt, float* __restrict__ AO) {
    extern __shared__ __half sm[];
    __half* Qs  = sm + QS_OFF;
    __half* Ks  = sm + KS_OFF;
    __half* Vts = sm + VT_OFF;

    const int tid = threadIdx.x;
    const int w = tid >> 5;
    const int l = tid & 31;
    const int g = l >> 2;
    const int t = l & 3;

    const int qt = blockIdx.x;
    const int h  = blockIdx.y;
    const int b  = blockIdx.z;

    const __half* Qg = Qh + ((size_t)b * SEQ + qt * 128) * DMODEL + h * DKH;
    const __half* Kg = Kh + (size_t)b * SEQ * DMODEL + h * DKH;
    const __half* Vg = Vt + (size_t)(b * NHEAD + h) * DKH * SEQ;

    #pragma unroll
    for (int j = 0; j < 4; j++) {
        int u = tid + 256 * j;
        int r = u >> 3, c8 = u & 7;
        uint4 v = *(const uint4*)(Qg + (size_t)r * DMODEL + c8 * 8);
        *(uint4*)&Qs[r * QS_LD + c8 * 8] = v;
    }

    float m0 = -1e30f, m1 = -1e30f, l0 = 0.f, l1 = 0.f;
    float o[8][4];
    #pragma unroll
    for (int dt = 0; dt < 8; dt++)
        #pragma unroll
        for (int c = 0; c < 4; c++) o[dt][c] = 0.f;

    const int r0 = 16 * w + g;

    for (int it = 0; it < SEQ / 128; it++) {
        __syncthreads();
        #pragma unroll
        for (int j = 0; j < 4; j++) {
            int u = tid + 256 * j;
            int r = u >> 3, c8 = u & 7;
            uint4 v = *(const uint4*)(Kg + ((size_t)(it * 128 + r)) * DMODEL + c8 * 8);
            *(uint4*)&Ks[r * KS_LD + c8 * 8] = v;
        }
        #pragma unroll
        for (int j = 0; j < 4; j++) {
            int u = tid + 256 * j;
            int d = u >> 4, c16 = u & 15;
            uint4 v = *(const uint4*)(Vg + (size_t)d * SEQ + it * 128 + c16 * 8);
            *(uint4*)&Vts[d * VT_LD + c16 * 8] = v;
        }
        __syncthreads();

        float s[16][4];
        #pragma unroll
        for (int nt = 0; nt < 16; nt++)
            #pragma unroll
            for (int c = 0; c < 4; c++) s[nt][c] = 0.f;

        #pragma unroll
        for (int ks = 0; ks < 4; ks++) {
            const int k0 = 16 * ks;
            uint32_t a[4];
            a[0] = *(const uint32_t*)&Qs[(r0)     * QS_LD + k0 + 2 * t];
            a[1] = *(const uint32_t*)&Qs[(r0 + 8) * QS_LD + k0 + 2 * t];
            a[2] = *(const uint32_t*)&Qs[(r0)     * QS_LD + k0 + 2 * t + 8];
            a[3] = *(const uint32_t*)&Qs[(r0 + 8) * QS_LD + k0 + 2 * t + 8];
            #pragma unroll
            for (int nt = 0; nt < 16; nt++) {
                uint32_t b0 = *(const uint32_t*)&Ks[(8 * nt + g) * KS_LD + k0 + 2 * t];
                uint32_t b1 = *(const uint32_t*)&Ks[(8 * nt + g) * KS_LD + k0 + 2 * t + 8];
                mma16816(s[nt], a, b0, b1);
            }
        }

        const float scale = 0.125f;
        float mx0 = -1e30f, mx1 = -1e30f;
        #pragma unroll
        for (int nt = 0; nt < 16; nt++) {
            s[nt][0] *= scale; s[nt][1] *= scale;
            s[nt][2] *= scale; s[nt][3] *= scale;
            mx0 = fmaxf(mx0, fmaxf(s[nt][0], s[nt][1]));
            mx1 = fmaxf(mx1, fmaxf(s[nt][2], s[nt][3]));
        }
        #pragma unroll
        for (int ofs = 1; ofs <= 2; ofs <<= 1) {
            mx0 = fmaxf(mx0, __shfl_xor_sync(0xffffffffu, mx0, ofs));
            mx1 = fmaxf(mx1, __shfl_xor_sync(0xffffffffu, mx1, ofs));
        }
        const float mn0 = fmaxf(m0, mx0);
        const float mn1 = fmaxf(m1, mx1);
        float rs0 = 0.f, rs1 = 0.f;
        #pragma unroll
        for (int nt = 0; nt < 16; nt++) {
            s[nt][0] = __expf(s[nt][0] - mn0);
            s[nt][1] = __expf(s[nt][1] - mn0);
            s[nt][2] = __expf(s[nt][2] - mn1);
            s[nt][3] = __expf(s[nt][3] - mn1);
            rs0 += s[nt][0] + s[nt][1];
            rs1 += s[nt][2] + s[nt][3];
        }
        #pragma unroll
        for (int ofs = 1; ofs <= 2; ofs <<= 1) {
            rs0 += __shfl_xor_sync(0xffffffffu, rs0, ofs);
            rs1 += __shfl_xor_sync(0xffffffffu, rs1, ofs);
        }
        const float al0 = __expf(m0 - mn0);
        const float al1 = __expf(m1 - mn1);
        l0 = l0 * al0 + rs0;  m0 = mn0;
        l1 = l1 * al1 + rs1;  m1 = mn1;
        #pragma unroll
        for (int dt = 0; dt < 8; dt++) {
            o[dt][0] *= al0; o[dt][1] *= al0;
            o[dt][2] *= al1; o[dt][3] *= al1;
        }

        #pragma unroll
        for (int ks = 0; ks < 8; ks++) {
            uint32_t a[4];
            a[0] = pack_h2(s[2 * ks][0],     s[2 * ks][1]);
            a[1] = pack_h2(s[2 * ks][2],     s[2 * ks][3]);
            a[2] = pack_h2(s[2 * ks + 1][0], s[2 * ks + 1][1]);
            a[3] = pack_h2(s[2 * ks + 1][2], s[2 * ks + 1][3]);
            const int k0 = 16 * ks;
            #pragma unroll
            for (int dt = 0; dt < 8; dt++) {
                uint32_t b0 = *(const uint32_t*)&Vts[(8 * dt + g) * VT_LD + k0 + 2 * t];
                uint32_t b1 = *(const uint32_t*)&Vts[(8 * dt + g) * VT_LD + k0 + 2 * t + 8];
                mma16816(o[dt], a, b0, b1);
            }
        }
    }

    float* Og = AO + ((size_t)b * SEQ + qt * 128) * DMODEL + h * DKH;
    const float inv0 = 1.f / l0, inv1 = 1.f / l1;
    #pragma unroll
    for (int dt = 0; dt < 8; dt++) {
        const int c = 8 * dt + 2 * t;
        *(float2*)(Og + (size_t)(r0)     * DMODEL + c) =
            make_float2(o[dt][0] * inv0, o[dt][1] * inv0);
        *(float2*)(Og + (size_t)(r0 + 8) * DMODEL + c) =
            make_float2(o[dt][2] * inv1, o[dt][3] * inv1);
    }
}

// ---------------------------------------------------------------------------
extern "C" void kernel_launch(void* const* d_in, const int* in_sizes, int n_in,
                              void* d_out, int out_size) {
    const float* q   = (const float*)d_in[0];
    const float* k   = (const float*)d_in[1];
    const float* v   = (const float*)d_in[2];
    const float* w_q = (const float*)d_in[3];
    const float* b_q = (const float*)d_in[4];
    const float* w_k = (const float*)d_in[5];
    const float* b_k = (const float*)d_in[6];
    const float* w_v = (const float*)d_in[7];
    const float* b_v = (const float*)d_in[8];
    const float* w_o = (const float*)d_in[9];
    const float* b_o = (const float*)d_in[10];

    __half *Qh, *Kh, *Vh, *Vt;
    float *AO;
    cudaGetSymbolAddress((void**)&Qh, g_Qh);
    cudaGetSymbolAddress((void**)&Kh, g_Kh);
    cudaGetSymbolAddress((void**)&Vh, g_Vh);
    cudaGetSymbolAddress((void**)&Vt, g_Vt);
    cudaGetSymbolAddress((void**)&AO, g_AO);

    cudaFuncSetAttribute(attn_kernel,
                         cudaFuncAttributeMaxDynamicSharedMemorySize,
                         ATTN_SMEM_BYTES);

    dim3 pgrid(MTOT / 128, DMODEL / 128);
    proj16_kernel<__half><<<pgrid, 256>>>(q, w_q, b_q, Qh);
    proj16_kernel<__half><<<pgrid, 256>>>(k, w_k, b_k, Kh);
    proj16_kernel<__half><<<pgrid, 256>>>(v, w_v, b_v, Vh);

    vtrans_kernel<<<dim3(SEQ / 32, DKH / 32, BATCH * NHEAD), dim3(32, 8)>>>(Vh, Vt);

    attn_kernel<<<dim3(SEQ / 128, NHEAD, BATCH), 256, ATTN_SMEM_BYTES>>>(Qh, Kh, Vt, AO);

    proj16_kernel<float><<<pgrid, 256>>>(AO, w_o, b_o, (float*)d_out);
}

// round 4
// speedup vs baseline: 5.7309x; 1.1918x over previous
#include <cuda_runtime.h>
#include <cuda_fp16.h>
#include <cstdint>

#define BATCH  2
#define SEQ    4096
#define DMODEL 512
#define NHEAD  8
#define DKH    64
#define MTOT   (BATCH * SEQ)

// fold 1/sqrt(64) * log2(e) into Q so softmax runs in log2 domain via ex2
#define QSCALE 0.1803368801111204f

// Scratch (__device__ globals: allocation-free rule)
__device__ __half g_Qh[(size_t)MTOT * DMODEL];
__device__ __half g_Kh[(size_t)MTOT * DMODEL];
__device__ __half g_Vh[(size_t)MTOT * DMODEL];
__device__ __half g_Vt[(size_t)MTOT * DMODEL];   // [b][h][d][s]
__device__ __half g_AOh[(size_t)MTOT * DMODEL];

// ---------------------------------------------------------------------------
// helpers
// ---------------------------------------------------------------------------
__device__ __forceinline__ void mma16816(float* d, const uint32_t* a,
                                         uint32_t b0, uint32_t b1) {
    asm volatile(
        "mma.sync.aligned.m16n8k16.row.col.f32.f16.f16.f32 "
        "{%0,%1,%2,%3}, {%4,%5,%6,%7}, {%8,%9}, {%0,%1,%2,%3};\n"
        : "+f"(d[0]), "+f"(d[1]), "+f"(d[2]), "+f"(d[3])
        : "r"(a[0]), "r"(a[1]), "r"(a[2]), "r"(a[3]), "r"(b0), "r"(b1));
}

__device__ __forceinline__ void ldsm_x4(uint32_t& r0, uint32_t& r1,
                                        uint32_t& r2, uint32_t& r3,
                                        uint32_t addr) {
    asm volatile(
        "ldmatrix.sync.aligned.m8n8.x4.shared.b16 {%0,%1,%2,%3}, [%4];"
        : "=r"(r0), "=r"(r1), "=r"(r2), "=r"(r3) : "r"(addr));
}

__device__ __forceinline__ uint32_t pack_h2(float x, float y) {
    __half2 h = __floats2half2_rn(x, y);
    return *(uint32_t*)&h;
}

__device__ __forceinline__ float ex2(float x) {
    float y;
    asm("ex2.approx.f32 %0, %1;" : "=f"(y) : "f"(x));
    return y;
}

__device__ __forceinline__ uint32_t smem_u32(const void* p) {
    return (uint32_t)__cvta_generic_to_shared(p);
}

#define CP16(dst, src) \
    asm volatile("cp.async.cg.shared.global [%0], [%1], 16;\n" \
                 :: "r"(dst), "l"(src) : "memory")

// ---------------------------------------------------------------------------
// Tensor-core projection GEMM: C[M,512] = A[M,512] @ W[512,512]^T + bias
// InT: float (cvt to fp16 in staging) or __half (direct copy).
// SCALE: multiply epilogue by QSCALE (Q projection).
// ---------------------------------------------------------------------------
#define PLD 72

template <typename InT, typename OutT, bool SCALE>
__global__ __launch_bounds__(256) void proj16_kernel(
        const InT* __restrict__ A, const float* __restrict__ W,
        const float* __restrict__ bias, OutT* __restrict__ C) {
    __shared__ __half As[128 * PLD];
    __shared__ __half Ws[128 * PLD];

    const int tid = threadIdx.x;
    const int w = tid >> 5;
    const int l = tid & 31;
    const int g = l >> 2;
    const int t = l & 3;
    const int wm = (w >> 1) * 32;
    const int wn = (w & 1) * 64;
    const int bm = blockIdx.x * 128;
    const int bn = blockIdx.y * 128;

    const int rowA = ((l >> 3) & 1) * 8 + (l & 7);
    const int colA = ((l >> 4) & 1) * 8;
    const int rowB = ((l >> 4) & 1) * 8 + (l & 7);
    const int colB = ((l >> 3) & 1) * 8;
    const uint32_t as_u = smem_u32(As);
    const uint32_t ws_u = smem_u32(Ws);

    float acc[2][8][4];
    #pragma unroll
    for (int mt = 0; mt < 2; mt++)
        #pragma unroll
        for (int nt = 0; nt < 8; nt++)
            #pragma unroll
            for (int c = 0; c < 4; c++) acc[mt][nt][c] = 0.f;

    for (int k0 = 0; k0 < DMODEL; k0 += 64) {
        // stage A
        if constexpr (sizeof(InT) == 2) {
            #pragma unroll
            for (int j = 0; j < 4; j++) {
                int u = tid + 256 * j;
                int r = u >> 3, c8 = u & 7;
                *(uint4*)&As[r * PLD + c8 * 8] =
                    *(const uint4*)((const __half*)A +
                                    (size_t)(bm + r) * DMODEL + k0 + c8 * 8);
            }
        } else {
            #pragma unroll
            for (int j = 0; j < 8; j++) {
                int u = tid + 256 * j;
                int r = u >> 4, c4 = u & 15;
                float4 va = *(const float4*)((const float*)A +
                                             (size_t)(bm + r) * DMODEL + k0 + c4 * 4);
                *(uint2*)&As[r * PLD + c4 * 4] =
                    make_uint2(pack_h2(va.x, va.y), pack_h2(va.z, va.w));
            }
        }
        // stage W (always fp32)
        #pragma unroll
        for (int j = 0; j < 8; j++) {
            int u = tid + 256 * j;
            int r = u >> 4, c4 = u & 15;
            float4 vb = *(const float4*)(W + (size_t)(bn + r) * DMODEL + k0 + c4 * 4);
            *(uint2*)&Ws[r * PLD + c4 * 4] =
                make_uint2(pack_h2(vb.x, vb.y), pack_h2(vb.z, vb.w));
        }
        __syncthreads();

        #pragma unroll
        for (int kk = 0; kk < 4; kk++) {
            const int ko = kk * 16;
            uint32_t a[2][4];
            #pragma unroll
            for (int mt = 0; mt < 2; mt++)
                ldsm_x4(a[mt][0], a[mt][1], a[mt][2], a[mt][3],
                        as_u + ((wm + 16 * mt + rowA) * PLD + ko + colA) * 2);
            #pragma unroll
            for (int p = 0; p < 4; p++) {
                uint32_t b0, b1, b2, b3;
                ldsm_x4(b0, b1, b2, b3,
                        ws_u + ((wn + 16 * p + rowB) * PLD + ko + colB) * 2);
                mma16816(acc[0][2 * p],     a[0], b0, b1);
                mma16816(acc[0][2 * p + 1], a[0], b2, b3);
                mma16816(acc[1][2 * p],     a[1], b0, b1);
                mma16816(acc[1][2 * p + 1], a[1], b2, b3);
            }
        }
        __syncthreads();
    }

    #pragma unroll
    for (int mt = 0; mt < 2; mt++) {
        const int r0 = bm + wm + 16 * mt + g;
        #pragma unroll
        for (int nt = 0; nt < 8; nt++) {
            const int c = bn + wn + 8 * nt + 2 * t;
            float o0 = acc[mt][nt][0] + bias[c];
            float o1 = acc[mt][nt][1] + bias[c + 1];
            float o2 = acc[mt][nt][2] + bias[c];
            float o3 = acc[mt][nt][3] + bias[c + 1];
            if constexpr (SCALE) {
                o0 *= QSCALE; o1 *= QSCALE; o2 *= QSCALE; o3 *= QSCALE;
            }
            if constexpr (sizeof(OutT) == 4) {
                *(float2*)((float*)C + (size_t)(r0)     * DMODEL + c) = make_float2(o0, o1);
                *(float2*)((float*)C + (size_t)(r0 + 8) * DMODEL + c) = make_float2(o2, o3);
            } else {
                *(uint32_t*)((__half*)C + (size_t)(r0)     * DMODEL + c) = pack_h2(o0, o1);
                *(uint32_t*)((__half*)C + (size_t)(r0 + 8) * DMODEL + c) = pack_h2(o2, o3);
            }
        }
    }
}

// ---------------------------------------------------------------------------
// V transpose: g_Vh [b][s][h*64+d] -> g_Vt [(b*8+h)*64+d][s]
// ---------------------------------------------------------------------------
__global__ void vtrans_kernel(const __half* __restrict__ Vh,
                              __half* __restrict__ Vt) {
    __shared__ __half tile[32][33];
    const int bh = blockIdx.z;
    const int b = bh >> 3, h = bh & 7;
    const int s0 = blockIdx.x * 32;
    const int d0 = blockIdx.y * 32;
    const int tx = threadIdx.x, ty = threadIdx.y;

    #pragma unroll
    for (int i = 0; i < 4; i++) {
        int s = s0 + ty + i * 8;
        tile[ty + i * 8][tx] =
            Vh[((size_t)b * SEQ + s) * DMODEL + h * DKH + d0 + tx];
    }
    __syncthreads();
    #pragma unroll
    for (int i = 0; i < 4; i++) {
        int d = d0 + ty + i * 8;
        Vt[((size_t)bh * DKH + d) * SEQ + s0 + tx] = tile[tx][ty + i * 8];
    }
}

// ---------------------------------------------------------------------------
// Flash attention: fp16 mma, fp32 accum, cp.async double-buffered K/V,
// ldmatrix fragment loads, log2-domain softmax (Q pre-scaled by QSCALE).
// ---------------------------------------------------------------------------
#define QS_LD 72
#define KS_LD 72
#define VT_LD 136
#define QS_OFF 0
#define KS_OFF (128 * QS_LD)                 // two K buffers
#define KS_STRIDE (128 * KS_LD)
#define VT_OFF (KS_OFF + 2 * KS_STRIDE)
#define VT_STRIDE (64 * VT_LD)
#define ATTN_SMEM_HALVES (VT_OFF + 2 * VT_STRIDE)
#define ATTN_SMEM_BYTES  (ATTN_SMEM_HALVES * 2)
#define NT (SEQ / 128)

__global__ __launch_bounds__(256, 1) void attn_kernel(
        const __half* __restrict__ Qh, const __half* __restrict__ Kh,
        const __half* __restrict__ Vt, __half* __restrict__ AO) {
    extern __shared__ __half sm[];
    __half* Qs = sm + QS_OFF;

    const int tid = threadIdx.x;
    const int w = tid >> 5;
    const int l = tid & 31;
    const int g = l >> 2;
    const int t = l & 3;

    const int qt = blockIdx.x;
    const int h  = blockIdx.y;
    const int b  = blockIdx.z;

    const __half* Qg = Qh + ((size_t)b * SEQ + qt * 128) * DMODEL + h * DKH;
    const __half* Kg = Kh + (size_t)b * SEQ * DMODEL + h * DKH;
    const __half* Vg = Vt + (size_t)(b * NHEAD + h) * DKH * SEQ;

    const int rowA = ((l >> 3) & 1) * 8 + (l & 7);
    const int colA = ((l >> 4) & 1) * 8;
    const int rowB = ((l >> 4) & 1) * 8 + (l & 7);
    const int colB = ((l >> 3) & 1) * 8;

    const uint32_t qs_u = smem_u32(sm) + QS_OFF * 2;
    uint32_t ks_u[2], vt_u[2];
    ks_u[0] = smem_u32(sm) + KS_OFF * 2;
    ks_u[1] = ks_u[0] + KS_STRIDE * 2;
    vt_u[0] = smem_u32(sm) + VT_OFF * 2;
    vt_u[1] = vt_u[0] + VT_STRIDE * 2;

    // Q tile (plain loads, once)
    #pragma unroll
    for (int j = 0; j < 4; j++) {
        int u = tid + 256 * j;
        int r = u >> 3, c8 = u & 7;
        *(uint4*)&Qs[r * QS_LD + c8 * 8] =
            *(const uint4*)(Qg + (size_t)r * DMODEL + c8 * 8);
    }

    // stage K/V tile `it` into buffer `bs`
    auto stage = [&](int it, int bs) {
        const __half* Kb = Kg + (size_t)(it * 128) * DMODEL;
        const uint32_t kd = ks_u[bs];
        #pragma unroll
        for (int j = 0; j < 4; j++) {
            int u = tid + 256 * j;
            int r = u >> 3, c8 = u & 7;
            CP16(kd + (r * KS_LD + c8 * 8) * 2, Kb + (size_t)r * DMODEL + c8 * 8);
        }
        const __half* Vb = Vg + it * 128;
        const uint32_t vd = vt_u[bs];
        #pragma unroll
        for (int j = 0; j < 4; j++) {
            int u = tid + 256 * j;
            int d = u >> 4, c16 = u & 15;
            CP16(vd + (d * VT_LD + c16 * 8) * 2, Vb + (size_t)d * SEQ + c16 * 8);
        }
        asm volatile("cp.async.commit_group;\n" ::: "memory");
    };

    stage(0, 0);

    float m0 = -1e30f, m1 = -1e30f, l0 = 0.f, l1 = 0.f;
    float o[8][4];
    #pragma unroll
    for (int dt = 0; dt < 8; dt++)
        #pragma unroll
        for (int c = 0; c < 4; c++) o[dt][c] = 0.f;

    const int r0 = 16 * w + g;

    for (int it = 0; it < NT; it++) {
        if (it + 1 < NT) {
            stage(it + 1, (it + 1) & 1);
            asm volatile("cp.async.wait_group 1;\n" ::: "memory");
        } else {
            asm volatile("cp.async.wait_group 0;\n" ::: "memory");
        }
        __syncthreads();

        const uint32_t kb = ks_u[it & 1];
        const uint32_t vb = vt_u[it & 1];

        // ---- S = Q @ K^T ----
        float s[16][4];
        #pragma unroll
        for (int nt = 0; nt < 16; nt++)
            #pragma unroll
            for (int c = 0; c < 4; c++) s[nt][c] = 0.f;

        #pragma unroll
        for (int ks = 0; ks < 4; ks++) {
            const int ko = 16 * ks;
            uint32_t a[4];
            ldsm_x4(a[0], a[1], a[2], a[3],
                    qs_u + ((16 * w + rowA) * QS_LD + ko + colA) * 2);
            #pragma unroll
            for (int p = 0; p < 8; p++) {
                uint32_t b0, b1, b2, b3;
                ldsm_x4(b0, b1, b2, b3,
                        kb + ((16 * p + rowB) * KS_LD + ko + colB) * 2);
                mma16816(s[2 * p],     a, b0, b1);
                mma16816(s[2 * p + 1], a, b2, b3);
            }
        }

        // ---- online softmax in log2 domain ----
        float mx0 = -1e30f, mx1 = -1e30f;
        #pragma unroll
        for (int nt = 0; nt < 16; nt++) {
            mx0 = fmaxf(mx0, fmaxf(s[nt][0], s[nt][1]));
            mx1 = fmaxf(mx1, fmaxf(s[nt][2], s[nt][3]));
        }
        #pragma unroll
        for (int ofs = 1; ofs <= 2; ofs <<= 1) {
            mx0 = fmaxf(mx0, __shfl_xor_sync(0xffffffffu, mx0, ofs));
            mx1 = fmaxf(mx1, __shfl_xor_sync(0xffffffffu, mx1, ofs));
        }
        const float mn0 = fmaxf(m0, mx0);
        const float mn1 = fmaxf(m1, mx1);
        float rs0 = 0.f, rs1 = 0.f;
        #pragma unroll
        for (int nt = 0; nt < 16; nt++) {
            s[nt][0] = ex2(s[nt][0] - mn0);
            s[nt][1] = ex2(s[nt][1] - mn0);
            s[nt][2] = ex2(s[nt][2] - mn1);
            s[nt][3] = ex2(s[nt][3] - mn1);
            rs0 += s[nt][0] + s[nt][1];
            rs1 += s[nt][2] + s[nt][3];
        }
        #pragma unroll
        for (int ofs = 1; ofs <= 2; ofs <<= 1) {
            rs0 += __shfl_xor_sync(0xffffffffu, rs0, ofs);
            rs1 += __shfl_xor_sync(0xffffffffu, rs1, ofs);
        }
        const float al0 = ex2(m0 - mn0);
        const float al1 = ex2(m1 - mn1);
        l0 = l0 * al0 + rs0;  m0 = mn0;
        l1 = l1 * al1 + rs1;  m1 = mn1;
        #pragma unroll
        for (int dt = 0; dt < 8; dt++) {
            o[dt][0] *= al0; o[dt][1] *= al0;
            o[dt][2] *= al1; o[dt][3] *= al1;
        }

        // ---- O += P @ V ----
        #pragma unroll
        for (int ks = 0; ks < 8; ks++) {
            uint32_t a[4];
            a[0] = pack_h2(s[2 * ks][0],     s[2 * ks][1]);
            a[1] = pack_h2(s[2 * ks][2],     s[2 * ks][3]);
            a[2] = pack_h2(s[2 * ks + 1][0], s[2 * ks + 1][1]);
            a[3] = pack_h2(s[2 * ks + 1][2], s[2 * ks + 1][3]);
            const int ko = 16 * ks;
            #pragma unroll
            for (int p = 0; p < 4; p++) {
                uint32_t b0, b1, b2, b3;
                ldsm_x4(b0, b1, b2, b3,
                        vb + ((16 * p + rowB) * VT_LD + ko + colB) * 2);
                mma16816(o[2 * p],     a, b0, b1);
                mma16816(o[2 * p + 1], a, b2, b3);
            }
        }
        __syncthreads();
    }

    // Epilogue: divide by l, write fp16
    __half* Og = AO + ((size_t)b * SEQ + qt * 128) * DMODEL + h * DKH;
    const float inv0 = 1.f / l0, inv1 = 1.f / l1;
    #pragma unroll
    for (int dt = 0; dt < 8; dt++) {
        const int c = 8 * dt + 2 * t;
        *(uint32_t*)(Og + (size_t)(r0)     * DMODEL + c) =
            pack_h2(o[dt][0] * inv0, o[dt][1] * inv0);
        *(uint32_t*)(Og + (size_t)(r0 + 8) * DMODEL + c) =
            pack_h2(o[dt][2] * inv1, o[dt][3] * inv1);
    }
}

// ---------------------------------------------------------------------------
extern "C" void kernel_launch(void* const* d_in, const int* in_sizes, int n_in,
                              void* d_out, int out_size) {
    const float* q   = (const float*)d_in[0];
    const float* k   = (const float*)d_in[1];
    const float* v   = (const float*)d_in[2];
    const float* w_q = (const float*)d_in[3];
    const float* b_q = (const float*)d_in[4];
    const float* w_k = (const float*)d_in[5];
    const float* b_k = (const float*)d_in[6];
    const float* w_v = (const float*)d_in[7];
    const float* b_v = (const float*)d_in[8];
    const float* w_o = (const float*)d_in[9];
    const float* b_o = (const float*)d_in[10];

    __half *Qh, *Kh, *Vh, *Vt, *AOh;
    cudaGetSymbolAddress((void**)&Qh,  g_Qh);
    cudaGetSymbolAddress((void**)&Kh,  g_Kh);
    cudaGetSymbolAddress((void**)&Vh,  g_Vh);
    cudaGetSymbolAddress((void**)&Vt,  g_Vt);
    cudaGetSymbolAddress((void**)&AOh, g_AOh);

    cudaFuncSetAttribute(attn_kernel,
                         cudaFuncAttributeMaxDynamicSharedMemorySize,
                         ATTN_SMEM_BYTES);

    dim3 pgrid(MTOT / 128, DMODEL / 128);
    proj16_kernel<float, __half, true ><<<pgrid, 256>>>(q, w_q, b_q, Qh);
    proj16_kernel<float, __half, false><<<pgrid, 256>>>(k, w_k, b_k, Kh);
    proj16_kernel<float, __half, false><<<pgrid, 256>>>(v, w_v, b_v, Vh);

    vtrans_kernel<<<dim3(SEQ / 32, DKH / 32, BATCH * NHEAD), dim3(32, 8)>>>(Vh, Vt);

    attn_kernel<<<dim3(SEQ / 128, NHEAD, BATCH), 256, ATTN_SMEM_BYTES>>>(Qh, Kh, Vt, AOh);

    proj16_kernel<__half, float, false><<<pgrid, 256>>>(AOh, w_o, b_o, (float*)d_out);
}

// round 5
// speedup vs baseline: 6.1088x; 1.0659x over previous
#include <cuda_runtime.h>
#include <cuda_fp16.h>
#include <cstdint>

#define BATCH  2
#define SEQ    4096
#define DMODEL 512
#define NHEAD  8
#define DKH    64
#define MTOT   (BATCH * SEQ)
#define DD     (DMODEL * DMODEL)

// fold 1/sqrt(64) * log2(e) into Q so softmax runs in log2 domain via ex2
#define QSCALE 0.1803368801111204f

// Scratch (__device__ globals: allocation-free rule)
__device__ __half g_Xq[(size_t)MTOT * DMODEL];   // fp16 copies of inputs
__device__ __half g_Xk[(size_t)MTOT * DMODEL];
__device__ __half g_Xv[(size_t)MTOT * DMODEL];
__device__ __half g_Wh[(size_t)4 * DD];          // fp16 copies of weights
__device__ __half g_Qh[(size_t)MTOT * DMODEL];
__device__ __half g_Kh[(size_t)MTOT * DMODEL];
__device__ __half g_Vh[(size_t)MTOT * DMODEL];
__device__ __half g_AOh[(size_t)MTOT * DMODEL];

// ---------------------------------------------------------------------------
// helpers
// ---------------------------------------------------------------------------
__device__ __forceinline__ void mma16816(float* d, const uint32_t* a,
                                         uint32_t b0, uint32_t b1) {
    asm volatile(
        "mma.sync.aligned.m16n8k16.row.col.f32.f16.f16.f32 "
        "{%0,%1,%2,%3}, {%4,%5,%6,%7}, {%8,%9}, {%0,%1,%2,%3};\n"
        : "+f"(d[0]), "+f"(d[1]), "+f"(d[2]), "+f"(d[3])
        : "r"(a[0]), "r"(a[1]), "r"(a[2]), "r"(a[3]), "r"(b0), "r"(b1));
}

__device__ __forceinline__ void ldsm_x4(uint32_t& r0, uint32_t& r1,
                                        uint32_t& r2, uint32_t& r3,
                                        uint32_t addr) {
    asm volatile(
        "ldmatrix.sync.aligned.m8n8.x4.shared.b16 {%0,%1,%2,%3}, [%4];"
        : "=r"(r0), "=r"(r1), "=r"(r2), "=r"(r3) : "r"(addr));
}

__device__ __forceinline__ void ldsm_x4_trans(uint32_t& r0, uint32_t& r1,
                                              uint32_t& r2, uint32_t& r3,
                                              uint32_t addr) {
    asm volatile(
        "ldmatrix.sync.aligned.m8n8.x4.trans.shared.b16 {%0,%1,%2,%3}, [%4];"
        : "=r"(r0), "=r"(r1), "=r"(r2), "=r"(r3) : "r"(addr));
}

__device__ __forceinline__ uint32_t pack_h2(float x, float y) {
    __half2 h = __floats2half2_rn(x, y);
    return *(uint32_t*)&h;
}

__device__ __forceinline__ float ex2(float x) {
    float y;
    asm("ex2.approx.f32 %0, %1;" : "=f"(y) : "f"(x));
    return y;
}

__device__ __forceinline__ uint32_t smem_u32(const void* p) {
    return (uint32_t)__cvta_generic_to_shared(p);
}

#define CP16(dst, src) \
    asm volatile("cp.async.cg.shared.global [%0], [%1], 16;\n" \
                 :: "r"(dst), "l"(src) : "memory")
#define CP_COMMIT() asm volatile("cp.async.commit_group;\n" ::: "memory")
#define CP_WAIT(n)  asm volatile("cp.async.wait_group %0;\n" :: "n"(n) : "memory")

// ---------------------------------------------------------------------------
// fp32 -> fp16 bulk convert (vectorized)
// ---------------------------------------------------------------------------
__global__ void cvt_kernel(const float4* __restrict__ src,
                           uint2* __restrict__ dst, int n4) {
    int i = blockIdx.x * blockDim.x + threadIdx.x;
    if (i < n4) {
        float4 v = src[i];
        dst[i] = make_uint2(pack_h2(v.x, v.y), pack_h2(v.z, v.w));
    }
}

// ---------------------------------------------------------------------------
// All-fp16 projection GEMM with cp.async 2-stage pipeline.
// C[M,512] = A[M,512] @ W[512,512]^T + bias ; CTA 128x128, BK=64, 8 warps.
// ---------------------------------------------------------------------------
#define PLD 72
#define PBUF (128 * PLD)                  // halves per stage buffer
#define PROJ_SMEM_BYTES (4 * PBUF * 2)    // As[2] + Ws[2]

template <typename OutT, bool SCALE>
__global__ __launch_bounds__(256) void proj16p_kernel(
        const __half* __restrict__ A, const __half* __restrict__ W,
        const float* __restrict__ bias, OutT* __restrict__ C) {
    extern __shared__ __half ps[];

    const int tid = threadIdx.x;
    const int w = tid >> 5;
    const int l = tid & 31;
    const int g = l >> 2;
    const int t = l & 3;
    const int wm = (w >> 1) * 32;
    const int wn = (w & 1) * 64;
    const int bm = blockIdx.x * 128;
    const int bn = blockIdx.y * 128;

    const int rowA = ((l >> 3) & 1) * 8 + (l & 7);
    const int colA = ((l >> 4) & 1) * 8;
    const int rowB = ((l >> 4) & 1) * 8 + (l & 7);
    const int colB = ((l >> 3) & 1) * 8;

    const uint32_t base_u = smem_u32(ps);
    uint32_t as_u[2], ws_u[2];
    as_u[0] = base_u;
    as_u[1] = base_u + PBUF * 2;
    ws_u[0] = base_u + 2 * PBUF * 2;
    ws_u[1] = base_u + 3 * PBUF * 2;

    const int sr = tid >> 3;          // staging row 0..31 (x4 passes -> 128)
    const int sc = (tid & 7) * 8;     // staging col (halves)

    auto stageP = [&](int ks, int bf) {
        const __half* Ab = A + (size_t)bm * DMODEL + ks * 64;
        const __half* Wb = W + (size_t)bn * DMODEL + ks * 64;
        const uint32_t ad = as_u[bf], wd = ws_u[bf];
        #pragma unroll
        for (int j = 0; j < 4; j++) {
            int r = sr + 32 * j;
            CP16(ad + (r * PLD + sc) * 2, Ab + (size_t)r * DMODEL + sc);
            CP16(wd + (r * PLD + sc) * 2, Wb + (size_t)r * DMODEL + sc);
        }
        CP_COMMIT();
    };

    float acc[2][8][4];
    #pragma unroll
    for (int mt = 0; mt < 2; mt++)
        #pragma unroll
        for (int nt = 0; nt < 8; nt++)
            #pragma unroll
            for (int c = 0; c < 4; c++) acc[mt][nt][c] = 0.f;

    stageP(0, 0);

    for (int ks = 0; ks < 8; ks++) {
        if (ks + 1 < 8) { stageP(ks + 1, (ks + 1) & 1); CP_WAIT(1); }
        else           { CP_WAIT(0); }
        __syncthreads();

        const uint32_t ab = as_u[ks & 1];
        const uint32_t wb = ws_u[ks & 1];

        #pragma unroll
        for (int kk = 0; kk < 4; kk++) {
            const int ko = kk * 16;
            uint32_t a[2][4];
            #pragma unroll
            for (int mt = 0; mt < 2; mt++)
                ldsm_x4(a[mt][0], a[mt][1], a[mt][2], a[mt][3],
                        ab + ((wm + 16 * mt + rowA) * PLD + ko + colA) * 2);
            #pragma unroll
            for (int p = 0; p < 4; p++) {
                uint32_t b0, b1, b2, b3;
                ldsm_x4(b0, b1, b2, b3,
                        wb + ((wn + 16 * p + rowB) * PLD + ko + colB) * 2);
                mma16816(acc[0][2 * p],     a[0], b0, b1);
                mma16816(acc[0][2 * p + 1], a[0], b2, b3);
                mma16816(acc[1][2 * p],     a[1], b0, b1);
                mma16816(acc[1][2 * p + 1], a[1], b2, b3);
            }
        }
        __syncthreads();
    }

    #pragma unroll
    for (int mt = 0; mt < 2; mt++) {
        const int r0 = bm + wm + 16 * mt + g;
        #pragma unroll
        for (int nt = 0; nt < 8; nt++) {
            const int c = bn + wn + 8 * nt + 2 * t;
            float o0 = acc[mt][nt][0] + bias[c];
            float o1 = acc[mt][nt][1] + bias[c + 1];
            float o2 = acc[mt][nt][2] + bias[c];
            float o3 = acc[mt][nt][3] + bias[c + 1];
            if constexpr (SCALE) {
                o0 *= QSCALE; o1 *= QSCALE; o2 *= QSCALE; o3 *= QSCALE;
            }
            if constexpr (sizeof(OutT) == 4) {
                *(float2*)((float*)C + (size_t)(r0)     * DMODEL + c) = make_float2(o0, o1);
                *(float2*)((float*)C + (size_t)(r0 + 8) * DMODEL + c) = make_float2(o2, o3);
            } else {
                *(uint32_t*)((__half*)C + (size_t)(r0)     * DMODEL + c) = pack_h2(o0, o1);
                *(uint32_t*)((__half*)C + (size_t)(r0 + 8) * DMODEL + c) = pack_h2(o2, o3);
            }
        }
    }
}

// ---------------------------------------------------------------------------
// Flash attention: fp16 mma, fp32 accum, cp.async double-buffered K/V,
// V^T fragments via ldmatrix.trans (no pre-transposed V needed),
// log2-domain softmax (Q pre-scaled by QSCALE).
// ---------------------------------------------------------------------------
#define TLD 72
#define TBUF (128 * TLD)
#define QS_OFF 0
#define KS_OFF TBUF
#define VS_OFF (KS_OFF + 2 * TBUF)
#define ATTN_SMEM_BYTES ((VS_OFF + 2 * TBUF) * 2)
#define NT (SEQ / 128)

__global__ __launch_bounds__(256, 1) void attn_kernel(
        const __half* __restrict__ Qh, const __half* __restrict__ Kh,
        const __half* __restrict__ Vh, __half* __restrict__ AO) {
    extern __shared__ __half sm[];
    __half* Qs = sm + QS_OFF;

    const int tid = threadIdx.x;
    const int w = tid >> 5;
    const int l = tid & 31;
    const int g = l >> 2;
    const int t = l & 3;

    const int qt = blockIdx.x;
    const int h  = blockIdx.y;
    const int b  = blockIdx.z;

    const __half* Qg = Qh + ((size_t)b * SEQ + qt * 128) * DMODEL + h * DKH;
    const __half* Kg = Kh + (size_t)b * SEQ * DMODEL + h * DKH;
    const __half* Vg = Vh + (size_t)b * SEQ * DMODEL + h * DKH;

    const int rowA = ((l >> 3) & 1) * 8 + (l & 7);
    const int colA = ((l >> 4) & 1) * 8;
    const int rowB = ((l >> 4) & 1) * 8 + (l & 7);
    const int colB = ((l >> 3) & 1) * 8;

    const uint32_t base_u = smem_u32(sm);
    const uint32_t qs_u = base_u;
    uint32_t ks_u[2], vs_u[2];
    ks_u[0] = base_u + KS_OFF * 2;
    ks_u[1] = ks_u[0] + TBUF * 2;
    vs_u[0] = base_u + VS_OFF * 2;
    vs_u[1] = vs_u[0] + TBUF * 2;

    // Q tile (plain loads, once)
    #pragma unroll
    for (int j = 0; j < 4; j++) {
        int u = tid + 256 * j;
        int r = u >> 3, c8 = u & 7;
        *(uint4*)&Qs[r * TLD + c8 * 8] =
            *(const uint4*)(Qg + (size_t)r * DMODEL + c8 * 8);
    }

    const int sr = tid >> 3;
    const int sc = (tid & 7) * 8;

    auto stage = [&](int it, int bs) {
        const __half* Kb = Kg + (size_t)(it * 128) * DMODEL;
        const __half* Vb = Vg + (size_t)(it * 128) * DMODEL;
        const uint32_t kd = ks_u[bs], vd = vs_u[bs];
        #pragma unroll
        for (int j = 0; j < 4; j++) {
            int r = sr + 32 * j;
            CP16(kd + (r * TLD + sc) * 2, Kb + (size_t)r * DMODEL + sc);
            CP16(vd + (r * TLD + sc) * 2, Vb + (size_t)r * DMODEL + sc);
        }
        CP_COMMIT();
    };

    stage(0, 0);

    float m0 = -1e30f, m1 = -1e30f, l0 = 0.f, l1 = 0.f;
    float o[8][4];
    #pragma unroll
    for (int dt = 0; dt < 8; dt++)
        #pragma unroll
        for (int c = 0; c < 4; c++) o[dt][c] = 0.f;

    const int r0 = 16 * w + g;

    for (int it = 0; it < NT; it++) {
        if (it + 1 < NT) { stage(it + 1, (it + 1) & 1); CP_WAIT(1); }
        else             { CP_WAIT(0); }
        __syncthreads();

        const uint32_t kb = ks_u[it & 1];
        const uint32_t vb = vs_u[it & 1];

        // ---- S = Q @ K^T ----
        float s[16][4];
        #pragma unroll
        for (int nt = 0; nt < 16; nt++)
            #pragma unroll
            for (int c = 0; c < 4; c++) s[nt][c] = 0.f;

        #pragma unroll
        for (int ks = 0; ks < 4; ks++) {
            const int ko = 16 * ks;
            uint32_t a[4];
            ldsm_x4(a[0], a[1], a[2], a[3],
                    qs_u + ((16 * w + rowA) * TLD + ko + colA) * 2);
            #pragma unroll
            for (int p = 0; p < 8; p++) {
                uint32_t b0, b1, b2, b3;
                ldsm_x4(b0, b1, b2, b3,
                        kb + ((16 * p + rowB) * TLD + ko + colB) * 2);
                mma16816(s[2 * p],     a, b0, b1);
                mma16816(s[2 * p + 1], a, b2, b3);
            }
        }

        // ---- online softmax in log2 domain ----
        float mx0 = -1e30f, mx1 = -1e30f;
        #pragma unroll
        for (int nt = 0; nt < 16; nt++) {
            mx0 = fmaxf(mx0, fmaxf(s[nt][0], s[nt][1]));
            mx1 = fmaxf(mx1, fmaxf(s[nt][2], s[nt][3]));
        }
        #pragma unroll
        for (int ofs = 1; ofs <= 2; ofs <<= 1) {
            mx0 = fmaxf(mx0, __shfl_xor_sync(0xffffffffu, mx0, ofs));
            mx1 = fmaxf(mx1, __shfl_xor_sync(0xffffffffu, mx1, ofs));
        }
        const float mn0 = fmaxf(m0, mx0);
        const float mn1 = fmaxf(m1, mx1);
        float rs0 = 0.f, rs1 = 0.f;
        #pragma unroll
        for (int nt = 0; nt < 16; nt++) {
            s[nt][0] = ex2(s[nt][0] - mn0);
            s[nt][1] = ex2(s[nt][1] - mn0);
            s[nt][2] = ex2(s[nt][2] - mn1);
            s[nt][3] = ex2(s[nt][3] - mn1);
            rs0 += s[nt][0] + s[nt][1];
            rs1 += s[nt][2] + s[nt][3];
        }
        #pragma unroll
        for (int ofs = 1; ofs <= 2; ofs <<= 1) {
            rs0 += __shfl_xor_sync(0xffffffffu, rs0, ofs);
            rs1 += __shfl_xor_sync(0xffffffffu, rs1, ofs);
        }
        const float al0 = ex2(m0 - mn0);
        const float al1 = ex2(m1 - mn1);
        l0 = l0 * al0 + rs0;  m0 = mn0;
        l1 = l1 * al1 + rs1;  m1 = mn1;
        #pragma unroll
        for (int dt = 0; dt < 8; dt++) {
            o[dt][0] *= al0; o[dt][1] *= al0;
            o[dt][2] *= al1; o[dt][3] *= al1;
        }

        // ---- O += P @ V ; V^T fragments via ldmatrix.trans ----
        #pragma unroll
        for (int ks = 0; ks < 8; ks++) {
            uint32_t a[4];
            a[0] = pack_h2(s[2 * ks][0],     s[2 * ks][1]);
            a[1] = pack_h2(s[2 * ks][2],     s[2 * ks][3]);
            a[2] = pack_h2(s[2 * ks + 1][0], s[2 * ks + 1][1]);
            a[3] = pack_h2(s[2 * ks + 1][2], s[2 * ks + 1][3]);
            const int ko = 16 * ks;
            #pragma unroll
            for (int p = 0; p < 4; p++) {
                uint32_t b0, b1, b2, b3;
                // fragment (n=d, k=kv) from V[kv][d]: rows=kv(ko+rowA), cols=d
                ldsm_x4_trans(b0, b1, b2, b3,
                              vb + ((ko + rowA) * TLD + 16 * p + colA) * 2);
                mma16816(o[2 * p],     a, b0, b1);
                mma16816(o[2 * p + 1], a, b2, b3);
            }
        }
        __syncthreads();
    }

    // Epilogue: divide by l, write fp16
    __half* Og = AO + ((size_t)b * SEQ + qt * 128) * DMODEL + h * DKH;
    const float inv0 = 1.f / l0, inv1 = 1.f / l1;
    #pragma unroll
    for (int dt = 0; dt < 8; dt++) {
        const int c = 8 * dt + 2 * t;
        *(uint32_t*)(Og + (size_t)(r0)     * DMODEL + c) =
            pack_h2(o[dt][0] * inv0, o[dt][1] * inv0);
        *(uint32_t*)(Og + (size_t)(r0 + 8) * DMODEL + c) =
            pack_h2(o[dt][2] * inv1, o[dt][3] * inv1);
    }
}

// ---------------------------------------------------------------------------
extern "C" void kernel_launch(void* const* d_in, const int* in_sizes, int n_in,
                              void* d_out, int out_size) {
    const float* q   = (const float*)d_in[0];
    const float* k   = (const float*)d_in[1];
    const float* v   = (const float*)d_in[2];
    const float* w_q = (const float*)d_in[3];
    const float* b_q = (const float*)d_in[4];
    const float* w_k = (const float*)d_in[5];
    const float* b_k = (const float*)d_in[6];
    const float* w_v = (const float*)d_in[7];
    const float* b_v = (const float*)d_in[8];
    const float* w_o = (const float*)d_in[9];
    const float* b_o = (const float*)d_in[10];

    __half *Xq, *Xk, *Xv, *Wh, *Qh, *Kh, *Vh, *AOh;
    cudaGetSymbolAddress((void**)&Xq,  g_Xq);
    cudaGetSymbolAddress((void**)&Xk,  g_Xk);
    cudaGetSymbolAddress((void**)&Xv,  g_Xv);
    cudaGetSymbolAddress((void**)&Wh,  g_Wh);
    cudaGetSymbolAddress((void**)&Qh,  g_Qh);
    cudaGetSymbolAddress((void**)&Kh,  g_Kh);
    cudaGetSymbolAddress((void**)&Vh,  g_Vh);
    cudaGetSymbolAddress((void**)&AOh, g_AOh);

    cudaFuncSetAttribute(attn_kernel,
                         cudaFuncAttributeMaxDynamicSharedMemorySize,
                         ATTN_SMEM_BYTES);
    cudaFuncSetAttribute(proj16p_kernel<__half, true>,
                         cudaFuncAttributeMaxDynamicSharedMemorySize,
                         PROJ_SMEM_BYTES);
    cudaFuncSetAttribute(proj16p_kernel<__half, false>,
                         cudaFuncAttributeMaxDynamicSharedMemorySize,
                         PROJ_SMEM_BYTES);
    cudaFuncSetAttribute(proj16p_kernel<float, false>,
                         cudaFuncAttributeMaxDynamicSharedMemorySize,
                         PROJ_SMEM_BYTES);

    // fp32 -> fp16 conversions
    const int nbig4 = (MTOT * DMODEL) / 4;   // 1,048,576
    const int nw4   = DD / 4;                // 65,536
    cvt_kernel<<<nbig4 / 256, 256>>>((const float4*)q, (uint2*)Xq, nbig4);
    cvt_kernel<<<nbig4 / 256, 256>>>((const float4*)k, (uint2*)Xk, nbig4);
    cvt_kernel<<<nbig4 / 256, 256>>>((const float4*)v, (uint2*)Xv, nbig4);
    cvt_kernel<<<nw4 / 256, 256>>>((const float4*)w_q, (uint2*)(Wh + 0 * (size_t)DD), nw4);
    cvt_kernel<<<nw4 / 256, 256>>>((const float4*)w_k, (uint2*)(Wh + 1 * (size_t)DD), nw4);
    cvt_kernel<<<nw4 / 256, 256>>>((const float4*)w_v, (uint2*)(Wh + 2 * (size_t)DD), nw4);
    cvt_kernel<<<nw4 / 256, 256>>>((const float4*)w_o, (uint2*)(Wh + 3 * (size_t)DD), nw4);

    dim3 pgrid(MTOT / 128, DMODEL / 128);
    proj16p_kernel<__half, true ><<<pgrid, 256, PROJ_SMEM_BYTES>>>(Xq, Wh + 0 * (size_t)DD, b_q, Qh);
    proj16p_kernel<__half, false><<<pgrid, 256, PROJ_SMEM_BYTES>>>(Xk, Wh + 1 * (size_t)DD, b_k, Kh);
    proj16p_kernel<__half, false><<<pgrid, 256, PROJ_SMEM_BYTES>>>(Xv, Wh + 2 * (size_t)DD, b_v, Vh);

    attn_kernel<<<dim3(SEQ / 128, NHEAD, BATCH), 256, ATTN_SMEM_BYTES>>>(Qh, Kh, Vh, AOh);

    proj16p_kernel<float, false><<<pgrid, 256, PROJ_SMEM_BYTES>>>(AOh, Wh + 3 * (size_t)DD, b_o, (float*)d_out);
}